// round 11
// baseline (speedup 1.0000x reference)
#include <cuda_runtime.h>
#include <math.h>

#define N_  256
#define M_  256
#define D_  256
#define E_  128
#define H_  4
#define HD_ 32
#define P_  64
#define CH_ 74    // key chunks per head (variable 3-4 tiles each)

// ---------------- packed fp32x2 helpers (Blackwell FFMA2 path) -----------
typedef unsigned long long u64;

__device__ __forceinline__ u64 pack2(float a, float b) {
    u64 r; asm("mov.b64 %0, {%1, %2};" : "=l"(r) : "f"(a), "f"(b)); return r;
}
__device__ __forceinline__ u64 dup2(float a) {
    u64 r; asm("mov.b64 %0, {%1, %1};" : "=l"(r) : "f"(a)); return r;
}
__device__ __forceinline__ void unpack2(u64 v, float& lo, float& hi) {
    asm("mov.b64 {%0, %1}, %2;" : "=f"(lo), "=f"(hi) : "l"(v));
}
__device__ __forceinline__ u64 fma2(u64 a, u64 b, u64 c) {
    u64 d; asm("fma.rn.f32x2 %0, %1, %2, %3;" : "=l"(d) : "l"(a), "l"(b), "l"(c)); return d;
}
__device__ __forceinline__ u64 add2(u64 a, u64 b) {
    u64 d; asm("add.rn.f32x2 %0, %1, %2;" : "=l"(d) : "l"(a), "l"(b)); return d;
}
__device__ __forceinline__ u64 mul2(u64 a, u64 b) {
    u64 d; asm("mul.rn.f32x2 %0, %1, %2;" : "=l"(d) : "l"(a), "l"(b)); return d;
}

// ---------------- device scratch (static, no allocations) ----------------
__device__ float d_qpe[N_*E_];                     // pos-MLP query embedding
__device__ float d_q[N_*E_];                       // scaled queries [N][E]
__device__ float d_phix[N_*E_], d_nphiy[M_*E_];    // nphiy = NEGATED phi_y
__device__ float d_gx[N_*E_],  d_ngy[M_*E_];       // ngy = NEGATED g_y
__device__ float d_Wkp[E_*P_], d_Wkg[E_*P_];       // folded MLP2 @ proj weights
__device__ float d_bkp[E_],    d_bkg[E_];
__device__ float d_pm[H_*CH_*N_], d_pl[H_*CH_*N_]; // partial softmax stats
__device__ float d_po[H_*CH_*N_*HD_];              // partial outputs

// chunk c tile range: heavy chunks (c<34) have 4 tiles, light have 3
__device__ __forceinline__ void chunk_range(int c, int& t0, int& t1) {
    if (c < 34) { t0 = 4*c;            t1 = t0 + 4; }
    else        { t0 = 136 + 3*(c-34); t1 = t0 + 3; }
}

// ---------------- A0: fold phi_w[:,D:] @ k_w2 -> Wkp / Wkg ---------------
__global__ void kfold(const float* __restrict__ phi_w, const float* __restrict__ g_w,
                      const float* __restrict__ k_w2, const float* __restrict__ k_b2) {
    int e = blockIdx.x, t = threadIdx.x;   // 128 threads
    if (t < 64) {
        float a = 0.f;
        for (int ep = 0; ep < 128; ep++)
            a = fmaf(phi_w[e*384 + 256 + ep], k_w2[ep*64 + t], a);
        d_Wkp[e*64 + t] = a;
    } else {
        int p = t - 64; float a = 0.f;
        for (int ep = 0; ep < 128; ep++)
            a = fmaf(g_w[e*384 + 256 + ep], k_w2[ep*64 + p], a);
        d_Wkg[e*64 + p] = a;
    }
    if (t == 0) {
        float a = 0.f;
        for (int ep = 0; ep < 128; ep++) a = fmaf(phi_w[e*384 + 256 + ep], k_b2[ep], a);
        d_bkp[e] = a;
    }
    if (t == 64) {
        float a = 0.f;
        for (int ep = 0; ep < 128; ep++) a = fmaf(g_w[e*384 + 256 + ep], k_b2[ep], a);
        d_bkg[e] = a;
    }
}

// ---------------- A1: query pos-MLP embedding (coalesced, smem-staged) ---
// grid 8, 256 threads. Block handles 32 queries.
__global__ void __launch_bounds__(256)
kqpe(const float* __restrict__ x_pos,
     const float* __restrict__ q_w1, const float* __restrict__ q_b1,
     const float* __restrict__ q_w2, const float* __restrict__ q_b2) {
    __shared__ float sW[128*65];   // q_w2 [e][p], pad 65
    __shared__ float hq[32*65];    // hidden [n][p], pad 65
    __shared__ float w1s[192], b1s[64], b2s[128];
    int t = threadIdx.x, n0 = blockIdx.x * 32;

    for (int i = t; i < 8192; i += 256) {        // coalesced q_w2 load
        int e = i >> 6, p = i & 63;
        sW[e*65 + p] = q_w2[i];
    }
    if (t < 192) w1s[t] = q_w1[t];
    if (t < 64)  b1s[t] = q_b1[t];
    if (t < 128) b2s[t] = q_b2[t];
    __syncthreads();

    for (int i = t; i < 2048; i += 256) {        // hidden layer
        int n = i >> 6, p = i & 63;
        float xp0 = x_pos[(n0+n)*3], xp1 = x_pos[(n0+n)*3+1], xp2 = x_pos[(n0+n)*3+2];
        hq[n*65 + p] = fmaxf(0.f, fmaf(w1s[p*3], xp0, fmaf(w1s[p*3+1], xp1,
                              fmaf(w1s[p*3+2], xp2, b1s[p]))));
    }
    __syncthreads();

    int ce = t & 31, rg = t >> 5;                // 8 groups of 4 rows
    float acc[4][4];
    #pragma unroll
    for (int i = 0; i < 4; i++)
        #pragma unroll
        for (int j = 0; j < 4; j++) acc[i][j] = b2s[ce + 32*j];
    for (int p = 0; p < 64; p++) {
        float w0 = sW[(ce     )*65 + p], w1 = sW[(ce+32)*65 + p];
        float w2 = sW[(ce+64)*65 + p],  w3 = sW[(ce+96)*65 + p];
        #pragma unroll
        for (int i = 0; i < 4; i++) {
            float xv = hq[(rg*4 + i)*65 + p];
            acc[i][0] = fmaf(xv, w0, acc[i][0]);
            acc[i][1] = fmaf(xv, w1, acc[i][1]);
            acc[i][2] = fmaf(xv, w2, acc[i][2]);
            acc[i][3] = fmaf(xv, w3, acc[i][3]);
        }
    }
    #pragma unroll
    for (int i = 0; i < 4; i++)
        #pragma unroll
        for (int j = 0; j < 4; j++)
            d_qpe[(n0 + rg*4 + i)*128 + ce + 32*j] = acc[i][j];
}

// ---------------- A2: tiled GEMM for q / phix / nphiy / gx / ngy ---------
// grid 40 (= 5 jobs x 8 row tiles of 32), 256 threads.
__global__ void __launch_bounds__(256)
kgemm(const float* __restrict__ x, const float* __restrict__ y,
      const float* __restrict__ theta_w, const float* __restrict__ phi_w,
      const float* __restrict__ g_w) {
    __shared__ float ws[128*65];   // weight tile [e][k], pad 65
    __shared__ float xs[32*65];    // act tile [n][k], pad 65
    int t = threadIdx.x;
    int job = blockIdx.x >> 3, rt = blockIdx.x & 7;
    int n0 = rt * 32;

    const float* W   = (job == 0) ? theta_w : (job <= 2 ? phi_w : g_w);
    const float* src = (job == 2 || job == 4) ? y : x;
    int   K    = (job == 0) ? 384 : 256;
    float mult = (job == 0) ? 0.17677669529663687f
               : (job == 2 || job == 4) ? -1.f : 1.f;
    float* out = (job == 0) ? d_q : (job == 1) ? d_phix : (job == 2) ? d_nphiy
               : (job == 3) ? d_gx : d_ngy;

    int ce = t & 31, rg = t >> 5;
    float acc[4][4];
    #pragma unroll
    for (int i = 0; i < 4; i++)
        #pragma unroll
        for (int j = 0; j < 4; j++) acc[i][j] = 0.f;

    for (int k0 = 0; k0 < K; k0 += 64) {
        for (int i = t; i < 8192; i += 256) {        // weight tile, coalesced
            int e = i >> 6, k = i & 63;
            ws[e*65 + k] = W[e*384 + k0 + k];
        }
        for (int i = t; i < 2048; i += 256) {        // activation tile
            int n = i >> 6, k = i & 63;
            float v;
            if (job == 0 && k0 >= 256) v = d_qpe[(n0+n)*128 + (k0 - 256) + k];
            else                       v = src[(n0+n)*256 + k0 + k];
            xs[n*65 + k] = v;
        }
        __syncthreads();
        #pragma unroll 4
        for (int k = 0; k < 64; k++) {
            float w0 = ws[(ce     )*65 + k], w1 = ws[(ce+32)*65 + k];
            float w2 = ws[(ce+64)*65 + k],  w3 = ws[(ce+96)*65 + k];
            #pragma unroll
            for (int i = 0; i < 4; i++) {
                float xv = xs[(rg*4 + i)*65 + k];
                acc[i][0] = fmaf(xv, w0, acc[i][0]);
                acc[i][1] = fmaf(xv, w1, acc[i][1]);
                acc[i][2] = fmaf(xv, w2, acc[i][2]);
                acc[i][3] = fmaf(xv, w3, acc[i][3]);
            }
        }
        __syncthreads();
    }
    #pragma unroll
    for (int i = 0; i < 4; i++)
        #pragma unroll
        for (int j = 0; j < 4; j++)
            out[(n0 + rg*4 + i)*128 + ce + 32*j] = acc[i][j] * mult;
}

// ---------------- B: fused kv-gen + flash attention ----------------------
// grid 296 CTAs, 128 threads. Thread t owns queries t and t+128, and
// generates key rows t and t+128 of each tile.
__global__ void __launch_bounds__(128, 2)
kattn(const float* __restrict__ x_pos, const float* __restrict__ y_pos,
      const float* __restrict__ k_w1, const float* __restrict__ k_b1) {
    extern __shared__ float sm[];
    float* ks   = sm;            // [256][36]
    float* vs   = sm + 9216;     // [256][36]
    float* WkpT = sm + 18432;    // [64][32]  (transposed head slice)
    float* WkgT = sm + 20480;    // [64][32]
    float* kw1s = sm + 22528;    // [64*3]
    float* kb1s = sm + 22720;    // [64]
    u64*   bkp2 = (u64*)(sm + 22784); // [16]
    u64*   bkg2 = bkp2 + 16;          // [16]   total 91392 bytes

    // bid -> (chunk, head). bids [0,136) heavy (4 tiles), [136,296) light (3).
    int bid = blockIdx.x, t = threadIdx.x;
    int c, h;
    if (bid < 136) { c = bid % 34; h = bid / 34; }       // heavy: c in [0,34)
    else {
        int u = bid - 136;                               // u in [0,160)
        c = 34 + (u % 40); h = u / 40;                   // light: c in [34,74)
    }
    int t0, t1; chunk_range(c, t0, t1);

    for (int i = t; i < 2048; i += 128) {
        int p = i >> 5, d = i & 31;
        WkpT[i] = d_Wkp[(h*32 + d)*64 + p];
        WkgT[i] = d_Wkg[(h*32 + d)*64 + p];
    }
    for (int i = t; i < 192; i += 128) kw1s[i] = k_w1[i];
    if (t < 64) kb1s[t] = k_b1[t];
    if (t < 16) bkp2[t] = pack2(d_bkp[h*32 + 2*t], d_bkp[h*32 + 2*t + 1]);
    else if (t < 32) { int j = t - 16; bkg2[j] = pack2(d_bkg[h*32 + 2*j], d_bkg[h*32 + 2*j + 1]); }
    __syncthreads();

    // two query softmax states + accumulators
    u64 oA[16], oB[16];
    #pragma unroll
    for (int i = 0; i < 16; i++) { oA[i] = 0ULL; oB[i] = 0ULL; }
    float mrA = -INFINITY, lrA = 0.f, mrB = -INFINITY, lrB = 0.f;

    // rel-pos anchors for the two key rows this thread generates
    float xpa0 = x_pos[t*3],       xpa1 = x_pos[t*3+1],       xpa2 = x_pos[t*3+2];
    float xpb0 = x_pos[(t+128)*3], xpb1 = x_pos[(t+128)*3+1], xpb2 = x_pos[(t+128)*3+2];

    for (int m = t0; m < t1; ++m) {
        float yp0 = y_pos[m*3], yp1 = y_pos[m*3+1], yp2 = y_pos[m*3+2];

        // ---- generate key+value rows t and t+128 of tile m ----
        #pragma unroll
        for (int rr = 0; rr < 2; rr++) {
            int row = t + 128*rr;
            float r0 = (rr ? xpb0 : xpa0) - yp0;
            float r1 = (rr ? xpb1 : xpa1) - yp1;
            float r2 = (rr ? xpb2 : xpa2) - yp2;

            u64 acc2[16];
            {   // k row
                const ulonglong2* px = (const ulonglong2*)(d_phix  + row*E_ + h*HD_);
                const ulonglong2* py = (const ulonglong2*)(d_nphiy + m*E_ + h*HD_);
                #pragma unroll
                for (int i = 0; i < 8; i++) {
                    ulonglong2 a = px[i], b = py[i];
                    acc2[2*i]   = add2(add2(a.x, b.x), bkp2[2*i]);
                    acc2[2*i+1] = add2(add2(a.y, b.y), bkp2[2*i+1]);
                }
            }
            #pragma unroll 4
            for (int p = 0; p < 64; p++) {
                float h1 = fmaxf(0.f, fmaf(kw1s[p*3], r0, fmaf(kw1s[p*3+1], r1,
                                fmaf(kw1s[p*3+2], r2, kb1s[p]))));
                u64 hh = dup2(h1);
                const ulonglong2* w = (const ulonglong2*)(WkpT + p*32);
                #pragma unroll
                for (int i = 0; i < 8; i++) {
                    ulonglong2 wv = w[i];
                    acc2[2*i]   = fma2(hh, wv.x, acc2[2*i]);
                    acc2[2*i+1] = fma2(hh, wv.y, acc2[2*i+1]);
                }
            }
            {
                ulonglong2* kd = (ulonglong2*)(ks + row*36);
                #pragma unroll
                for (int i = 0; i < 8; i++) kd[i] = make_ulonglong2(acc2[2*i], acc2[2*i+1]);
            }
            {   // v row
                const ulonglong2* px = (const ulonglong2*)(d_gx  + row*E_ + h*HD_);
                const ulonglong2* py = (const ulonglong2*)(d_ngy + m*E_ + h*HD_);
                #pragma unroll
                for (int i = 0; i < 8; i++) {
                    ulonglong2 a = px[i], b = py[i];
                    acc2[2*i]   = add2(add2(a.x, b.x), bkg2[2*i]);
                    acc2[2*i+1] = add2(add2(a.y, b.y), bkg2[2*i+1]);
                }
            }
            #pragma unroll 4
            for (int p = 0; p < 64; p++) {
                float h1 = fmaxf(0.f, fmaf(kw1s[p*3], r0, fmaf(kw1s[p*3+1], r1,
                                fmaf(kw1s[p*3+2], r2, kb1s[p]))));
                u64 hh = dup2(h1);
                const ulonglong2* w = (const ulonglong2*)(WkgT + p*32);
                #pragma unroll
                for (int i = 0; i < 8; i++) {
                    ulonglong2 wv = w[i];
                    acc2[2*i]   = fma2(hh, wv.x, acc2[2*i]);
                    acc2[2*i+1] = fma2(hh, wv.y, acc2[2*i+1]);
                }
            }
            {
                ulonglong2* vd = (ulonglong2*)(vs + row*36);
                #pragma unroll
                for (int i = 0; i < 8; i++) vd[i] = make_ulonglong2(acc2[2*i], acc2[2*i+1]);
            }
        }
        __syncthreads();

        // ---- load both queries (after gen; keeps gen-phase regs low) ----
        u64 qA[16], qB[16];
        {
            const ulonglong2* qp = (const ulonglong2*)(d_q + t*E_ + h*HD_);
            const ulonglong2* qq = (const ulonglong2*)(d_q + (t+128)*E_ + h*HD_);
            #pragma unroll
            for (int i = 0; i < 8; i++) {
                ulonglong2 v = qp[i]; qA[2*i] = v.x; qA[2*i+1] = v.y;
                ulonglong2 w = qq[i]; qB[2*i] = w.x; qB[2*i+1] = w.y;
            }
        }

        // ---- online-softmax attention over this 256-key tile ----
        for (int kb = 0; kb < 256; kb += 8) {
            float sA[8], sB[8];
            #pragma unroll
            for (int k8 = 0; k8 < 8; k8++) {
                const ulonglong2* kk = (const ulonglong2*)(ks + (kb + k8)*36);
                u64 aa = 0ULL, ab = 0ULL, ba = 0ULL, bb = 0ULL;
                #pragma unroll
                for (int i = 0; i < 8; i++) {
                    ulonglong2 kv = kk[i];
                    aa = fma2(qA[2*i],   kv.x, aa);
                    ab = fma2(qA[2*i+1], kv.y, ab);
                    ba = fma2(qB[2*i],   kv.x, ba);
                    bb = fma2(qB[2*i+1], kv.y, bb);
                }
                float l0, h0, l1, h1;
                unpack2(aa, l0, h0); unpack2(ab, l1, h1);
                sA[k8] = (l0 + h0) + (l1 + h1);
                unpack2(ba, l0, h0); unpack2(bb, l1, h1);
                sB[k8] = (l0 + h0) + (l1 + h1);
            }
            float mnA = mrA, mnB = mrB;
            #pragma unroll
            for (int k8 = 0; k8 < 8; k8++) { mnA = fmaxf(mnA, sA[k8]); mnB = fmaxf(mnB, sB[k8]); }
            float scA = __expf(mrA - mnA), scB = __expf(mrB - mnB);
            float lsA = 0.f, lsB = 0.f;
            #pragma unroll
            for (int k8 = 0; k8 < 8; k8++) {
                sA[k8] = __expf(sA[k8] - mnA); lsA += sA[k8];
                sB[k8] = __expf(sB[k8] - mnB); lsB += sB[k8];
            }
            lrA = fmaf(lrA, scA, lsA); mrA = mnA;
            lrB = fmaf(lrB, scB, lsB); mrB = mnB;
            u64 s2A = dup2(scA), s2B = dup2(scB);
            #pragma unroll
            for (int i = 0; i < 16; i++) { oA[i] = mul2(oA[i], s2A); oB[i] = mul2(oB[i], s2B); }
            #pragma unroll
            for (int k8 = 0; k8 < 8; k8++) {
                const ulonglong2* vv = (const ulonglong2*)(vs + (kb + k8)*36);
                u64 pA = dup2(sA[k8]), pB = dup2(sB[k8]);
                #pragma unroll
                for (int i = 0; i < 8; i++) {
                    ulonglong2 v = vv[i];
                    oA[2*i]   = fma2(pA, v.x, oA[2*i]);
                    oA[2*i+1] = fma2(pA, v.y, oA[2*i+1]);
                    oB[2*i]   = fma2(pB, v.x, oB[2*i]);
                    oB[2*i+1] = fma2(pB, v.y, oB[2*i+1]);
                }
            }
        }
        __syncthreads();
    }

    int baseA = (h*CH_ + c)*N_ + t;
    int baseB = baseA + 128;
    d_pm[baseA] = mrA; d_pl[baseA] = lrA;
    d_pm[baseB] = mrB; d_pl[baseB] = lrB;
    ulonglong2* opA = (ulonglong2*)(d_po + (size_t)baseA*32);
    ulonglong2* opB = (ulonglong2*)(d_po + (size_t)baseB*32);
    #pragma unroll
    for (int i = 0; i < 8; i++) {
        opA[i] = make_ulonglong2(oA[2*i], oA[2*i+1]);
        opB[i] = make_ulonglong2(oB[2*i], oB[2*i+1]);
    }
}

// ---------------- C: combine + out-proj + residual + layernorm -----------
__global__ void kfinal(const float* __restrict__ x, const float* __restrict__ out_w,
                       const float* __restrict__ ln_g, const float* __restrict__ ln_b,
                       float* __restrict__ out) {
    int n = blockIdx.x, t = threadIdx.x;   // 256 threads
    __shared__ float so[128];
    __shared__ float red[256], red2[256];
    if (t < 128) {
        int h = t >> 5, d = t & 31;
        float Mx = -INFINITY;
        #pragma unroll 2
        for (int c = 0; c < CH_; c++)
            Mx = fmaxf(Mx, d_pm[(h*CH_ + c)*N_ + n]);
        float L = 0.f, oa = 0.f;
        #pragma unroll 2
        for (int c = 0; c < CH_; c++) {
            int b = (h*CH_ + c)*N_ + n;
            float e = __expf(d_pm[b] - Mx);
            L  = fmaf(d_pl[b], e, L);
            oa = fmaf(d_po[(size_t)b*32 + d], e, oa);
        }
        so[t] = oa / L;
    }
    __syncthreads();
    float r = x[n*256 + t];
    const float* wr = out_w + t*128;
    #pragma unroll 8
    for (int e = 0; e < 128; e++) r = fmaf(so[e], wr[e], r);
    red[t] = r; red2[t] = r*r;
    __syncthreads();
    for (int s = 128; s > 0; s >>= 1) {
        if (t < s) { red[t] += red[t + s]; red2[t] += red2[t + s]; }
        __syncthreads();
    }
    float mu  = red[0] * (1.f/256.f);
    float var = red2[0] * (1.f/256.f) - mu*mu;
    float inv = rsqrtf(var + 1e-5f);
    out[n*256 + t] = (r - mu) * inv * ln_g[t] + ln_b[t];
}

// ---------------- launch --------------------------------------------------
extern "C" void kernel_launch(void* const* d_in, const int* in_sizes, int n_in,
                              void* d_out, int out_size) {
    const float* x       = (const float*)d_in[0];
    const float* y       = (const float*)d_in[1];
    const float* x_pos   = (const float*)d_in[2];
    const float* y_pos   = (const float*)d_in[3];
    const float* theta_w = (const float*)d_in[4];
    const float* phi_w   = (const float*)d_in[5];
    const float* g_w     = (const float*)d_in[6];
    const float* q_w1    = (const float*)d_in[7];
    const float* q_b1    = (const float*)d_in[8];
    const float* q_w2    = (const float*)d_in[9];
    const float* q_b2    = (const float*)d_in[10];
    const float* k_w1    = (const float*)d_in[11];
    const float* k_b1    = (const float*)d_in[12];
    const float* k_w2    = (const float*)d_in[13];
    const float* k_b2    = (const float*)d_in[14];
    const float* out_w   = (const float*)d_in[15];
    const float* ln_g    = (const float*)d_in[16];
    const float* ln_b    = (const float*)d_in[17];
    float* out = (float*)d_out;

    cudaFuncSetAttribute(kattn, cudaFuncAttributeMaxDynamicSharedMemorySize, 91392);

    kfold<<<128, 128>>>(phi_w, g_w, k_w2, k_b2);
    kqpe<<<8, 256>>>(x_pos, q_w1, q_b1, q_w2, q_b2);
    kgemm<<<40, 256>>>(x, y, theta_w, phi_w, g_w);
    kattn<<<296, 128, 91392>>>(x_pos, y_pos, k_w1, k_b1);
    kfinal<<<256, 256>>>(x, out_w, ln_g, ln_b, out);
}

// round 12
// speedup vs baseline: 1.5499x; 1.5499x over previous
#include <cuda_runtime.h>
#include <math.h>

#define N_  256
#define M_  256
#define D_  256
#define E_  128
#define H_  4
#define HD_ 32
#define P_  64
#define CH_ 74    // key chunks per head (variable 3-4 tiles each)

// ---------------- packed fp32x2 helpers (Blackwell FFMA2 path) -----------
typedef unsigned long long u64;

__device__ __forceinline__ u64 pack2(float a, float b) {
    u64 r; asm("mov.b64 %0, {%1, %2};" : "=l"(r) : "f"(a), "f"(b)); return r;
}
__device__ __forceinline__ u64 dup2(float a) {
    u64 r; asm("mov.b64 %0, {%1, %1};" : "=l"(r) : "f"(a)); return r;
}
__device__ __forceinline__ void unpack2(u64 v, float& lo, float& hi) {
    asm("mov.b64 {%0, %1}, %2;" : "=f"(lo), "=f"(hi) : "l"(v));
}
__device__ __forceinline__ u64 fma2(u64 a, u64 b, u64 c) {
    u64 d; asm("fma.rn.f32x2 %0, %1, %2, %3;" : "=l"(d) : "l"(a), "l"(b), "l"(c)); return d;
}
__device__ __forceinline__ u64 add2(u64 a, u64 b) {
    u64 d; asm("add.rn.f32x2 %0, %1, %2;" : "=l"(d) : "l"(a), "l"(b)); return d;
}
__device__ __forceinline__ u64 mul2(u64 a, u64 b) {
    u64 d; asm("mul.rn.f32x2 %0, %1, %2;" : "=l"(d) : "l"(a), "l"(b)); return d;
}

// ---------------- device scratch (static, no allocations) ----------------
__device__ float d_qpe[N_*E_];                     // pos-MLP query embedding
__device__ float d_q[N_*E_];                       // scaled queries [N][E]
__device__ float d_phix[N_*E_], d_nphiy[M_*E_];    // nphiy = NEGATED phi_y
__device__ float d_gx[N_*E_],  d_ngy[M_*E_];       // ngy = NEGATED g_y
__device__ float d_Wkp[E_*P_], d_Wkg[E_*P_];       // folded MLP2 @ proj weights
__device__ float d_bkp[E_],    d_bkg[E_];
__device__ float d_pm[H_*CH_*N_], d_pl[H_*CH_*N_]; // partial softmax stats
__device__ float d_po[H_*CH_*N_*HD_];              // partial outputs

// chunk c tile range: heavy chunks (c<34) have 4 tiles, light have 3
__device__ __forceinline__ void chunk_range(int c, int& t0, int& t1) {
    if (c < 34) { t0 = 4*c;            t1 = t0 + 4; }
    else        { t0 = 136 + 3*(c-34); t1 = t0 + 3; }
}

// ---------------- A0: fold phi_w[:,D:] @ k_w2 -> Wkp / Wkg ---------------
__global__ void kfold(const float* __restrict__ phi_w, const float* __restrict__ g_w,
                      const float* __restrict__ k_w2, const float* __restrict__ k_b2) {
    int e = blockIdx.x, t = threadIdx.x;   // 128 threads
    if (t < 64) {
        float a = 0.f;
        for (int ep = 0; ep < 128; ep++)
            a = fmaf(phi_w[e*384 + 256 + ep], k_w2[ep*64 + t], a);
        d_Wkp[e*64 + t] = a;
    } else {
        int p = t - 64; float a = 0.f;
        for (int ep = 0; ep < 128; ep++)
            a = fmaf(g_w[e*384 + 256 + ep], k_w2[ep*64 + p], a);
        d_Wkg[e*64 + p] = a;
    }
    if (t == 0) {
        float a = 0.f;
        for (int ep = 0; ep < 128; ep++) a = fmaf(phi_w[e*384 + 256 + ep], k_b2[ep], a);
        d_bkp[e] = a;
    }
    if (t == 64) {
        float a = 0.f;
        for (int ep = 0; ep < 128; ep++) a = fmaf(g_w[e*384 + 256 + ep], k_b2[ep], a);
        d_bkg[e] = a;
    }
}

// ---------------- A1: query pos-MLP embedding (coalesced, smem-staged) ---
// grid 8, 256 threads. Block handles 32 queries.
__global__ void __launch_bounds__(256)
kqpe(const float* __restrict__ x_pos,
     const float* __restrict__ q_w1, const float* __restrict__ q_b1,
     const float* __restrict__ q_w2, const float* __restrict__ q_b2) {
    __shared__ float sW[128*65];   // q_w2 [e][p], pad 65
    __shared__ float hq[32*65];    // hidden [n][p], pad 65
    __shared__ float w1s[192], b1s[64], b2s[128];
    int t = threadIdx.x, n0 = blockIdx.x * 32;

    for (int i = t; i < 8192; i += 256) {        // coalesced q_w2 load
        int e = i >> 6, p = i & 63;
        sW[e*65 + p] = q_w2[i];
    }
    if (t < 192) w1s[t] = q_w1[t];
    if (t < 64)  b1s[t] = q_b1[t];
    if (t < 128) b2s[t] = q_b2[t];
    __syncthreads();

    for (int i = t; i < 2048; i += 256) {        // hidden layer
        int n = i >> 6, p = i & 63;
        float xp0 = x_pos[(n0+n)*3], xp1 = x_pos[(n0+n)*3+1], xp2 = x_pos[(n0+n)*3+2];
        hq[n*65 + p] = fmaxf(0.f, fmaf(w1s[p*3], xp0, fmaf(w1s[p*3+1], xp1,
                              fmaf(w1s[p*3+2], xp2, b1s[p]))));
    }
    __syncthreads();

    int ce = t & 31, rg = t >> 5;                // 8 groups of 4 rows
    float acc[4][4];
    #pragma unroll
    for (int i = 0; i < 4; i++)
        #pragma unroll
        for (int j = 0; j < 4; j++) acc[i][j] = b2s[ce + 32*j];
    for (int p = 0; p < 64; p++) {
        float w0 = sW[(ce     )*65 + p], w1 = sW[(ce+32)*65 + p];
        float w2 = sW[(ce+64)*65 + p],  w3 = sW[(ce+96)*65 + p];
        #pragma unroll
        for (int i = 0; i < 4; i++) {
            float xv = hq[(rg*4 + i)*65 + p];
            acc[i][0] = fmaf(xv, w0, acc[i][0]);
            acc[i][1] = fmaf(xv, w1, acc[i][1]);
            acc[i][2] = fmaf(xv, w2, acc[i][2]);
            acc[i][3] = fmaf(xv, w3, acc[i][3]);
        }
    }
    #pragma unroll
    for (int i = 0; i < 4; i++)
        #pragma unroll
        for (int j = 0; j < 4; j++)
            d_qpe[(n0 + rg*4 + i)*128 + ce + 32*j] = acc[i][j];
}

// ---------------- A2: tiled GEMM for q / phix / nphiy / gx / ngy ---------
// grid 40 (= 5 jobs x 8 row tiles of 32), 256 threads.
__global__ void __launch_bounds__(256)
kgemm(const float* __restrict__ x, const float* __restrict__ y,
      const float* __restrict__ theta_w, const float* __restrict__ phi_w,
      const float* __restrict__ g_w) {
    __shared__ float ws[128*65];   // weight tile [e][k], pad 65
    __shared__ float xs[32*65];    // act tile [n][k], pad 65
    int t = threadIdx.x;
    int job = blockIdx.x >> 3, rt = blockIdx.x & 7;
    int n0 = rt * 32;

    const float* W   = (job == 0) ? theta_w : (job <= 2 ? phi_w : g_w);
    const float* src = (job == 2 || job == 4) ? y : x;
    int   K    = (job == 0) ? 384 : 256;
    float mult = (job == 0) ? 0.17677669529663687f
               : (job == 2 || job == 4) ? -1.f : 1.f;
    float* out = (job == 0) ? d_q : (job == 1) ? d_phix : (job == 2) ? d_nphiy
               : (job == 3) ? d_gx : d_ngy;

    int ce = t & 31, rg = t >> 5;
    float acc[4][4];
    #pragma unroll
    for (int i = 0; i < 4; i++)
        #pragma unroll
        for (int j = 0; j < 4; j++) acc[i][j] = 0.f;

    for (int k0 = 0; k0 < K; k0 += 64) {
        for (int i = t; i < 8192; i += 256) {        // weight tile, coalesced
            int e = i >> 6, k = i & 63;
            ws[e*65 + k] = W[e*384 + k0 + k];
        }
        for (int i = t; i < 2048; i += 256) {        // activation tile
            int n = i >> 6, k = i & 63;
            float v;
            if (job == 0 && k0 >= 256) v = d_qpe[(n0+n)*128 + (k0 - 256) + k];
            else                       v = src[(n0+n)*256 + k0 + k];
            xs[n*65 + k] = v;
        }
        __syncthreads();
        #pragma unroll 4
        for (int k = 0; k < 64; k++) {
            float w0 = ws[(ce     )*65 + k], w1 = ws[(ce+32)*65 + k];
            float w2 = ws[(ce+64)*65 + k],  w3 = ws[(ce+96)*65 + k];
            #pragma unroll
            for (int i = 0; i < 4; i++) {
                float xv = xs[(rg*4 + i)*65 + k];
                acc[i][0] = fmaf(xv, w0, acc[i][0]);
                acc[i][1] = fmaf(xv, w1, acc[i][1]);
                acc[i][2] = fmaf(xv, w2, acc[i][2]);
                acc[i][3] = fmaf(xv, w3, acc[i][3]);
            }
        }
        __syncthreads();
    }
    #pragma unroll
    for (int i = 0; i < 4; i++)
        #pragma unroll
        for (int j = 0; j < 4; j++)
            out[(n0 + rg*4 + i)*128 + ce + 32*j] = acc[i][j] * mult;
}

// ---------------- B: fused kv-gen + flash attention (2 queries/thread) ---
// grid 296 CTAs, 128 threads. Thread t owns queries t and t+128, and
// generates key rows t and t+128 of each tile. Inner key loops use
// LIMITED unrolling so ptxas doesn't hoist 8 keys of LDS into registers
// (that hoist is what spiked regs to 255 / spilled in the previous build).
__global__ void __launch_bounds__(128, 2)
kattn(const float* __restrict__ x_pos, const float* __restrict__ y_pos,
      const float* __restrict__ k_w1, const float* __restrict__ k_b1) {
    extern __shared__ float sm[];
    float* ks   = sm;            // [256][36]
    float* vs   = sm + 9216;     // [256][36]
    float* WkpT = sm + 18432;    // [64][32]  (transposed head slice)
    float* WkgT = sm + 20480;    // [64][32]
    float* kw1s = sm + 22528;    // [64*3]
    float* kb1s = sm + 22720;    // [64]
    u64*   bkp2 = (u64*)(sm + 22784); // [16]
    u64*   bkg2 = bkp2 + 16;          // [16]   total 91392 bytes

    int bid = blockIdx.x, t = threadIdx.x;
    int c, h;
    if (bid < 136) { c = bid % 34; h = bid / 34; }       // heavy: c in [0,34)
    else {
        int u = bid - 136;                               // u in [0,160)
        c = 34 + (u % 40); h = u / 40;                   // light: c in [34,74)
    }
    int t0, t1; chunk_range(c, t0, t1);

    for (int i = t; i < 2048; i += 128) {
        int p = i >> 5, d = i & 31;
        WkpT[i] = d_Wkp[(h*32 + d)*64 + p];
        WkgT[i] = d_Wkg[(h*32 + d)*64 + p];
    }
    for (int i = t; i < 192; i += 128) kw1s[i] = k_w1[i];
    if (t < 64) kb1s[t] = k_b1[t];
    if (t < 16) bkp2[t] = pack2(d_bkp[h*32 + 2*t], d_bkp[h*32 + 2*t + 1]);
    else if (t < 32) { int j = t - 16; bkg2[j] = pack2(d_bkg[h*32 + 2*j], d_bkg[h*32 + 2*j + 1]); }
    __syncthreads();

    u64 oA[16], oB[16];
    #pragma unroll
    for (int i = 0; i < 16; i++) { oA[i] = 0ULL; oB[i] = 0ULL; }
    float mrA = -INFINITY, lrA = 0.f, mrB = -INFINITY, lrB = 0.f;

    float xpa0 = x_pos[t*3],       xpa1 = x_pos[t*3+1],       xpa2 = x_pos[t*3+2];
    float xpb0 = x_pos[(t+128)*3], xpb1 = x_pos[(t+128)*3+1], xpb2 = x_pos[(t+128)*3+2];

    for (int m = t0; m < t1; ++m) {
        float yp0 = y_pos[m*3], yp1 = y_pos[m*3+1], yp2 = y_pos[m*3+2];

        // ---- generate key+value rows t and t+128 of tile m ----
        #pragma unroll 1
        for (int rr = 0; rr < 2; rr++) {
            int row = t + 128*rr;
            float r0 = (rr ? xpb0 : xpa0) - yp0;
            float r1 = (rr ? xpb1 : xpa1) - yp1;
            float r2 = (rr ? xpb2 : xpa2) - yp2;

            u64 acc2[16];
            {   // k row
                const ulonglong2* px = (const ulonglong2*)(d_phix  + row*E_ + h*HD_);
                const ulonglong2* py = (const ulonglong2*)(d_nphiy + m*E_ + h*HD_);
                #pragma unroll
                for (int i = 0; i < 8; i++) {
                    ulonglong2 a = px[i], b = py[i];
                    acc2[2*i]   = add2(add2(a.x, b.x), bkp2[2*i]);
                    acc2[2*i+1] = add2(add2(a.y, b.y), bkp2[2*i+1]);
                }
            }
            #pragma unroll 4
            for (int p = 0; p < 64; p++) {
                float h1 = fmaxf(0.f, fmaf(kw1s[p*3], r0, fmaf(kw1s[p*3+1], r1,
                                fmaf(kw1s[p*3+2], r2, kb1s[p]))));
                u64 hh = dup2(h1);
                const ulonglong2* w = (const ulonglong2*)(WkpT + p*32);
                #pragma unroll
                for (int i = 0; i < 8; i++) {
                    ulonglong2 wv = w[i];
                    acc2[2*i]   = fma2(hh, wv.x, acc2[2*i]);
                    acc2[2*i+1] = fma2(hh, wv.y, acc2[2*i+1]);
                }
            }
            {
                ulonglong2* kd = (ulonglong2*)(ks + row*36);
                #pragma unroll
                for (int i = 0; i < 8; i++) kd[i] = make_ulonglong2(acc2[2*i], acc2[2*i+1]);
            }
            {   // v row
                const ulonglong2* px = (const ulonglong2*)(d_gx  + row*E_ + h*HD_);
                const ulonglong2* py = (const ulonglong2*)(d_ngy + m*E_ + h*HD_);
                #pragma unroll
                for (int i = 0; i < 8; i++) {
                    ulonglong2 a = px[i], b = py[i];
                    acc2[2*i]   = add2(add2(a.x, b.x), bkg2[2*i]);
                    acc2[2*i+1] = add2(add2(a.y, b.y), bkg2[2*i+1]);
                }
            }
            #pragma unroll 4
            for (int p = 0; p < 64; p++) {
                float h1 = fmaxf(0.f, fmaf(kw1s[p*3], r0, fmaf(kw1s[p*3+1], r1,
                                fmaf(kw1s[p*3+2], r2, kb1s[p]))));
                u64 hh = dup2(h1);
                const ulonglong2* w = (const ulonglong2*)(WkgT + p*32);
                #pragma unroll
                for (int i = 0; i < 8; i++) {
                    ulonglong2 wv = w[i];
                    acc2[2*i]   = fma2(hh, wv.x, acc2[2*i]);
                    acc2[2*i+1] = fma2(hh, wv.y, acc2[2*i+1]);
                }
            }
            {
                ulonglong2* vd = (ulonglong2*)(vs + row*36);
                #pragma unroll
                for (int i = 0; i < 8; i++) vd[i] = make_ulonglong2(acc2[2*i], acc2[2*i+1]);
            }
        }
        __syncthreads();

        // ---- load both queries ----
        u64 qA[16], qB[16];
        {
            const ulonglong2* qp = (const ulonglong2*)(d_q + t*E_ + h*HD_);
            const ulonglong2* qq = (const ulonglong2*)(d_q + (t+128)*E_ + h*HD_);
            #pragma unroll
            for (int i = 0; i < 8; i++) {
                ulonglong2 v = qp[i]; qA[2*i] = v.x; qA[2*i+1] = v.y;
                ulonglong2 w = qq[i]; qB[2*i] = w.x; qB[2*i+1] = w.y;
            }
        }

        // ---- online-softmax attention over this 256-key tile ----
        #pragma unroll 1
        for (int kb = 0; kb < 256; kb += 8) {
            float sA[8], sB[8];
            #pragma unroll 2
            for (int k8 = 0; k8 < 8; k8++) {
                const ulonglong2* kk = (const ulonglong2*)(ks + (kb + k8)*36);
                u64 aa = 0ULL, ab = 0ULL, ba = 0ULL, bb = 0ULL;
                #pragma unroll
                for (int i = 0; i < 8; i++) {
                    ulonglong2 kv = kk[i];
                    aa = fma2(qA[2*i],   kv.x, aa);
                    ab = fma2(qA[2*i+1], kv.y, ab);
                    ba = fma2(qB[2*i],   kv.x, ba);
                    bb = fma2(qB[2*i+1], kv.y, bb);
                }
                float l0, h0, l1, h1;
                unpack2(aa, l0, h0); unpack2(ab, l1, h1);
                sA[k8] = (l0 + h0) + (l1 + h1);
                unpack2(ba, l0, h0); unpack2(bb, l1, h1);
                sB[k8] = (l0 + h0) + (l1 + h1);
            }
            float mnA = mrA, mnB = mrB;
            #pragma unroll
            for (int k8 = 0; k8 < 8; k8++) { mnA = fmaxf(mnA, sA[k8]); mnB = fmaxf(mnB, sB[k8]); }
            float scA = __expf(mrA - mnA), scB = __expf(mrB - mnB);
            float lsA = 0.f, lsB = 0.f;
            #pragma unroll
            for (int k8 = 0; k8 < 8; k8++) {
                sA[k8] = __expf(sA[k8] - mnA); lsA += sA[k8];
                sB[k8] = __expf(sB[k8] - mnB); lsB += sB[k8];
            }
            lrA = fmaf(lrA, scA, lsA); mrA = mnA;
            lrB = fmaf(lrB, scB, lsB); mrB = mnB;
            u64 s2A = dup2(scA), s2B = dup2(scB);
            #pragma unroll
            for (int i = 0; i < 16; i++) { oA[i] = mul2(oA[i], s2A); oB[i] = mul2(oB[i], s2B); }
            #pragma unroll 2
            for (int k8 = 0; k8 < 8; k8++) {
                const ulonglong2* vv = (const ulonglong2*)(vs + (kb + k8)*36);
                u64 pA = dup2(sA[k8]), pB = dup2(sB[k8]);
                #pragma unroll
                for (int i = 0; i < 8; i++) {
                    ulonglong2 v = vv[i];
                    oA[2*i]   = fma2(pA, v.x, oA[2*i]);
                    oA[2*i+1] = fma2(pA, v.y, oA[2*i+1]);
                    oB[2*i]   = fma2(pB, v.x, oB[2*i]);
                    oB[2*i+1] = fma2(pB, v.y, oB[2*i+1]);
                }
            }
        }
        __syncthreads();
    }

    int baseA = (h*CH_ + c)*N_ + t;
    int baseB = baseA + 128;
    d_pm[baseA] = mrA; d_pl[baseA] = lrA;
    d_pm[baseB] = mrB; d_pl[baseB] = lrB;
    ulonglong2* opA = (ulonglong2*)(d_po + (size_t)baseA*32);
    ulonglong2* opB = (ulonglong2*)(d_po + (size_t)baseB*32);
    #pragma unroll
    for (int i = 0; i < 8; i++) {
        opA[i] = make_ulonglong2(oA[2*i], oA[2*i+1]);
        opB[i] = make_ulonglong2(oB[2*i], oB[2*i+1]);
    }
}

// ---------------- C: combine + out-proj + residual + layernorm -----------
__global__ void kfinal(const float* __restrict__ x, const float* __restrict__ out_w,
                       const float* __restrict__ ln_g, const float* __restrict__ ln_b,
                       float* __restrict__ out) {
    int n = blockIdx.x, t = threadIdx.x;   // 256 threads
    __shared__ float so[128];
    __shared__ float red[256], red2[256];
    if (t < 128) {
        int h = t >> 5, d = t & 31;
        float Mx = -INFINITY;
        #pragma unroll 2
        for (int c = 0; c < CH_; c++)
            Mx = fmaxf(Mx, d_pm[(h*CH_ + c)*N_ + n]);
        float L = 0.f, oa = 0.f;
        #pragma unroll 2
        for (int c = 0; c < CH_; c++) {
            int b = (h*CH_ + c)*N_ + n;
            float e = __expf(d_pm[b] - Mx);
            L  = fmaf(d_pl[b], e, L);
            oa = fmaf(d_po[(size_t)b*32 + d], e, oa);
        }
        so[t] = oa / L;
    }
    __syncthreads();
    float r = x[n*256 + t];
    const float* wr = out_w + t*128;
    #pragma unroll 8
    for (int e = 0; e < 128; e++) r = fmaf(so[e], wr[e], r);
    red[t] = r; red2[t] = r*r;
    __syncthreads();
    for (int s = 128; s > 0; s >>= 1) {
        if (t < s) { red[t] += red[t + s]; red2[t] += red2[t + s]; }
        __syncthreads();
    }
    float mu  = red[0] * (1.f/256.f);
    float var = red2[0] * (1.f/256.f) - mu*mu;
    float inv = rsqrtf(var + 1e-5f);
    out[n*256 + t] = (r - mu) * inv * ln_g[t] + ln_b[t];
}

// ---------------- launch --------------------------------------------------
extern "C" void kernel_launch(void* const* d_in, const int* in_sizes, int n_in,
                              void* d_out, int out_size) {
    const float* x       = (const float*)d_in[0];
    const float* y       = (const float*)d_in[1];
    const float* x_pos   = (const float*)d_in[2];
    const float* y_pos   = (const float*)d_in[3];
    const float* theta_w = (const float*)d_in[4];
    const float* phi_w   = (const float*)d_in[5];
    const float* g_w     = (const float*)d_in[6];
    const float* q_w1    = (const float*)d_in[7];
    const float* q_b1    = (const float*)d_in[8];
    const float* q_w2    = (const float*)d_in[9];
    const float* q_b2    = (const float*)d_in[10];
    const float* k_w1    = (const float*)d_in[11];
    const float* k_b1    = (const float*)d_in[12];
    const float* k_w2    = (const float*)d_in[13];
    const float* k_b2    = (const float*)d_in[14];
    const float* out_w   = (const float*)d_in[15];
    const float* ln_g    = (const float*)d_in[16];
    const float* ln_b    = (const float*)d_in[17];
    float* out = (float*)d_out;

    cudaFuncSetAttribute(kattn, cudaFuncAttributeMaxDynamicSharedMemorySize, 91392);

    kfold<<<128, 128>>>(phi_w, g_w, k_w2, k_b2);
    kqpe<<<8, 256>>>(x_pos, q_w1, q_b1, q_w2, q_b2);
    kgemm<<<40, 256>>>(x, y, theta_w, phi_w, g_w);
    kattn<<<296, 128, 91392>>>(x_pos, y_pos, k_w1, k_b1);
    kfinal<<<256, 256>>>(x, out_w, ln_g, ln_b, out);
}